// round 11
// baseline (speedup 1.0000x reference)
#include <cuda_runtime.h>
#include <cuda_bf16.h>
#include <math.h>

// Problem constants (fixed by the dataset): B=128, S=1024, d=64, D=64.
#define S_LEN   1024
#define NSTEP   512     // fused pair steps; ring depth must divide NSTEP
#define D_DIM   64
#define NSYM    64
#define NPAIR   (NSYM * NSYM)
#define DEPTH   4       // ring buffers; prefetch distance 3; 512 % 4 == 0

// Pair table, bf16, stored in CONSUMPTION ORDER for the 2-warp main kernel:
// tile(p) is 8KB; uint4 index = p*512 + W*256 + m*32 + l, holding elements
// i = 8m..8m+7 of row j = 32W + l, value = pairT[p][j][i]
// (= sum_j' core[s1][i][j'] * core[s2][j'][j]).  Consumer warp W lane l reads
// its row with 8 LDG.128, each a coalesced 512B warp transaction.
__device__ __nv_bfloat16 g_pairT[NPAIR * D_DIM * D_DIM];

__device__ __forceinline__ unsigned long long ffma2(unsigned long long a,
                                                    unsigned long long b,
                                                    unsigned long long c) {
    unsigned long long d;
    asm("fma.rn.f32x2 %0, %1, %2, %3;" : "=l"(d) : "l"(a), "l"(b), "l"(c));
    return d;
}
__device__ __forceinline__ unsigned long long packdup(float x) {
    unsigned long long d;
    asm("mov.b64 %0, {%1, %1};" : "=l"(d) : "f"(x));
    return d;
}
// pack two f32 into one bf16x2 u32: low 16 = lo (even index), high 16 = hi
__device__ __forceinline__ unsigned int bfpack(float lo, float hi) {
    unsigned int r;
    asm("cvt.rn.satfinite.bf16x2.f32 %0, %1, %2;" : "=r"(r) : "f"(hi), "f"(lo));
    return r;
}
// reinterpret a u32 as bf16x2 (via union; no pointer aliasing)
__device__ __forceinline__ __nv_bfloat162 u2bf2(unsigned int u) {
    union { unsigned int ui; __nv_bfloat162 b2; } cv;
    cv.ui = u;
    return cv.b2;
}

// ---------------------------------------------------------------------------
// Prep: build the 4096-pair table (8i x 4k register tiling, FMA-bound).
// One CTA (128 threads) per (s1,s2).  tid -> kb = tid&15 (k0=4*kb),
// ib = tid>>4 (i0=8*ib).  Identical math to R8; ONLY the output store index
// changed to the new consumption layout.
// ---------------------------------------------------------------------------
__global__ __launch_bounds__(128) void ttrain_pair_kernel(
    const float* __restrict__ core)
{
    const int p  = blockIdx.x;
    const int s1 = p >> 6;
    const int s2 = p & 63;

    __shared__ float AT[D_DIM * D_DIM];   // AT[j][i] = core[s1][i][j]
    __shared__ float Bs[D_DIM * D_DIM];   // Bs[j][k] = core[s2][j][k]

    const int tid = threadIdx.x;
    const float4* A4 = reinterpret_cast<const float4*>(core + (s1 << 12));
    const float4* B4 = reinterpret_cast<const float4*>(core + (s2 << 12));
    float4* Bs4 = reinterpret_cast<float4*>(Bs);

#pragma unroll
    for (int v = tid; v < 1024; v += 128) Bs4[v] = B4[v];
#pragma unroll
    for (int v = tid; v < 1024; v += 128) {
        float4 a = A4[v];
        int i = v >> 4;
        int jj = (v & 15) << 2;
        AT[ jj      * 64 + i] = a.x;
        AT[(jj + 1) * 64 + i] = a.y;
        AT[(jj + 2) * 64 + i] = a.z;
        AT[(jj + 3) * 64 + i] = a.w;
    }
    __syncthreads();

    const int kb = tid & 15;
    const int ib = tid >> 4;
    const int k0 = kb << 2;     // this thread: k0..k0+3
    const int i0 = ib << 3;     // this thread: i0..i0+7

    unsigned long long acc[4][4];   // [kk][i-pair], f32x2
#pragma unroll
    for (int a = 0; a < 4; ++a)
#pragma unroll
        for (int m = 0; m < 4; ++m) acc[a][m] = 0ull;

#pragma unroll 4
    for (int jj = 0; jj < 64; ++jj) {
        float4 b4 = *reinterpret_cast<const float4*>(Bs + jj * 64 + k0);
        unsigned long long bd0 = packdup(b4.x);
        unsigned long long bd1 = packdup(b4.y);
        unsigned long long bd2 = packdup(b4.z);
        unsigned long long bd3 = packdup(b4.w);
        const ulonglong2* av =
            reinterpret_cast<const ulonglong2*>(AT + jj * 64 + i0);
        ulonglong2 a01 = av[0], a23 = av[1];
        acc[0][0] = ffma2(a01.x, bd0, acc[0][0]);
        acc[0][1] = ffma2(a01.y, bd0, acc[0][1]);
        acc[0][2] = ffma2(a23.x, bd0, acc[0][2]);
        acc[0][3] = ffma2(a23.y, bd0, acc[0][3]);
        acc[1][0] = ffma2(a01.x, bd1, acc[1][0]);
        acc[1][1] = ffma2(a01.y, bd1, acc[1][1]);
        acc[1][2] = ffma2(a23.x, bd1, acc[1][2]);
        acc[1][3] = ffma2(a23.y, bd1, acc[1][3]);
        acc[2][0] = ffma2(a01.x, bd2, acc[2][0]);
        acc[2][1] = ffma2(a01.y, bd2, acc[2][1]);
        acc[2][2] = ffma2(a23.x, bd2, acc[2][2]);
        acc[2][3] = ffma2(a23.y, bd2, acc[2][3]);
        acc[3][0] = ffma2(a01.x, bd3, acc[3][0]);
        acc[3][1] = ffma2(a01.y, bd3, acc[3][1]);
        acc[3][2] = ffma2(a23.x, bd3, acc[3][2]);
        acc[3][3] = ffma2(a23.y, bd3, acc[3][3]);
    }

    // Store in the 2-warp consumption layout: row j = k, chunk m = i0>>3:
    // uint4 index = p*512 + (k>>5)*256 + (i0>>3)*32 + (k&31).
    uint4* out4 = reinterpret_cast<uint4*>(g_pairT);
#pragma unroll
    for (int kk = 0; kk < 4; ++kk) {
        const int k = k0 + kk;
        float2 f0 = *reinterpret_cast<float2*>(&acc[kk][0]);
        float2 f1 = *reinterpret_cast<float2*>(&acc[kk][1]);
        float2 f2 = *reinterpret_cast<float2*>(&acc[kk][2]);
        float2 f3 = *reinterpret_cast<float2*>(&acc[kk][3]);
        uint4 v = make_uint4(bfpack(f0.x, f0.y), bfpack(f1.x, f1.y),
                             bfpack(f2.x, f2.y), bfpack(f3.x, f3.y));
        out4[(p << 9) + ((k >> 5) << 8) + ((i0 >> 3) << 5) + (k & 31)] = v;
    }
}

// ---------------------------------------------------------------------------
// Main chain v3: 2 warps per CTA, one chain per CTA, ONE j PER LANE.
// Lane l of warp W owns output j = 32W + l and computes the full 64-term
// i-sum in-lane: 8 broadcast LDS.128 of bf16 c + 32 HFMA2 against its
// prefetched weight row (8 coalesced LDG.128, distance-3 ring), hadd2 tree,
// one st.shared.u16.  No shfl, no cross-lane combine.
// Renorm each step: exact power-of-two scale from exponent of c[0] (taken
// from carr[0].x low half - no extra load); cancels exactly in the final log.
// ---------------------------------------------------------------------------
__global__ __launch_bounds__(64, 1) void ttrain_main_kernel(
    const int*   __restrict__ X,
    const float* __restrict__ lb,
    const float* __restrict__ rb,
    float*       __restrict__ out)
{
    __shared__ __align__(16) unsigned short s_c[2][D_DIM];  // bf16 c, dbl-buf
    __shared__ float s_red[2];
    __shared__ int   sP[NSTEP];

    const int tid = threadIdx.x;
    const int b   = blockIdx.x;
    const int W   = tid >> 5;
    const int l   = tid & 31;
    const int j   = tid;            // one output column per thread

    // Stage fused pair indices: pidx[t] = X[2t]*64 + X[2t+1].
    const int2* Xb2 = reinterpret_cast<const int2*>(X + b * S_LEN);
    for (int k = tid; k < NSTEP; k += 64) {
        int2 x2 = Xb2[k];
        sP[k] = (x2.x << 6) | x2.y;
    }
    s_c[0][tid] = __bfloat16_as_ushort(__float2bfloat16(lb[tid]));
    __syncthreads();

    // My weight row in the permuted layout: uint4 idx = p*512 + W*256 + m*32 + l.
    const uint4* wbase = reinterpret_cast<const uint4*>(g_pairT);
    const int    toff  = (W << 8) + l;

    uint4 ring[DEPTH][8];
#define LOADW(dst, tt) {                                                   \
        const uint4* pw_ = wbase + (sP[(tt) & (NSTEP - 1)] << 9) + toff;   \
        (dst)[0] = pw_[0];   (dst)[1] = pw_[32];                           \
        (dst)[2] = pw_[64];  (dst)[3] = pw_[96];                           \
        (dst)[4] = pw_[128]; (dst)[5] = pw_[160];                          \
        (dst)[6] = pw_[192]; (dst)[7] = pw_[224]; }

    LOADW(ring[0], 0)
    LOADW(ring[1], 1)
    LOADW(ring[2], 2)

    int e_total = 0;

    for (int t0 = 0; t0 < NSTEP; t0 += DEPTH) {    // NSTEP % DEPTH == 0
#pragma unroll
        for (int u = 0; u < DEPTH; ++u) {
            const int t   = t0 + u;
            const int buf = t & 1;

            // Whole c vector (64 bf16 = 128B): 8 broadcast LDS.128.
            const uint4* cv4 = reinterpret_cast<const uint4*>(&s_c[buf][0]);
            uint4 carr[8];
#pragma unroll
            for (int m = 0; m < 8; ++m) carr[m] = cv4[m];

            // Prefetch step t+3 (off the critical path).
            LOADW(ring[(u + DEPTH - 1) % DEPTH], t + DEPTH - 1)

            // Renorm scale from c[0]'s exponent (low bf16 of carr[0].x).
            int ef = (carr[0].x >> 7) & 0xff;
            int e  = (ef == 0) ? 0 : ef - 127;
            e = e < -96 ? -96 : (e > 96 ? 96 : e);
            e_total += e;
            const float scale = __int_as_float((127 - e) << 23);

            const uint4* wq = ring[u];

            __nv_bfloat162 a0 = __float2bfloat162_rn(0.f);
            __nv_bfloat162 a1 = __float2bfloat162_rn(0.f);
            __nv_bfloat162 a2 = __float2bfloat162_rn(0.f);
            __nv_bfloat162 a3 = __float2bfloat162_rn(0.f);
#pragma unroll
            for (int m = 0; m < 8; ++m) {
                a0 = __hfma2(u2bf2(carr[m].x), u2bf2(wq[m].x), a0);
                a1 = __hfma2(u2bf2(carr[m].y), u2bf2(wq[m].y), a1);
                a2 = __hfma2(u2bf2(carr[m].z), u2bf2(wq[m].z), a2);
                a3 = __hfma2(u2bf2(carr[m].w), u2bf2(wq[m].w), a3);
            }
            __nv_bfloat162 s01 = __hadd2(a0, a1);
            __nv_bfloat162 s23 = __hadd2(a2, a3);
            __nv_bfloat162 st  = __hadd2(s01, s23);
            float tot = __bfloat162float(__low2bfloat16(st)) +
                        __bfloat162float(__high2bfloat16(st));

            unsigned short cn =
                __bfloat16_as_ushort(__float2bfloat16(tot * scale));
            s_c[buf ^ 1][j] = cn;
            __syncthreads();
        }
    }
#undef LOADW

    // Final contraction with right boundary + log-likelihood.
    float v = __bfloat162float(__ushort_as_bfloat16(s_c[0][tid])) * rb[tid];
#pragma unroll
    for (int o = 16; o >= 1; o >>= 1)
        v += __shfl_xor_sync(0xffffffffu, v, o);
    if (l == 0) s_red[W] = v;
    __syncthreads();
    if (tid == 0) {
        double ov = (double)s_red[0] + (double)s_red[1];
        out[b] = (float)(2.0 * ((double)e_total * 0.6931471805599453 +
                                log(fabs(ov))));
    }
}

extern "C" void kernel_launch(void* const* d_in, const int* in_sizes, int n_in,
                              void* d_out, int out_size) {
    // metadata order: X [128*1024] i32, core [64*64*64] f32,
    //                 left_boundary [64] f32, right_boundary [64] f32
    const int*   X    = (const int*)  d_in[0];
    const float* core = (const float*)d_in[1];
    const float* lb   = (const float*)d_in[2];
    const float* rb   = (const float*)d_in[3];
    float*       out  = (float*)d_out;

    ttrain_pair_kernel<<<NPAIR, 128>>>(core);
    ttrain_main_kernel<<<128, 64>>>(X, lb, rb, out);
}

// round 13
// speedup vs baseline: 1.5865x; 1.5865x over previous
#include <cuda_runtime.h>
#include <cuda_bf16.h>
#include <math.h>
#include <stdint.h>

// Problem constants (fixed by the dataset): B=128, S=1024, d=64, D=64.
#define S_LEN   1024
#define NSTEP   512     // fused pair steps; ring depth must divide NSTEP
#define D_DIM   64
#define NSYM    64
#define NPAIR   (NSYM * NSYM)
#define DEPTH   4       // ring buffers; prefetch distance 3; 512 % 4 == 0
#define PADROW  72      // smem row stride in bf16 (144B: conflict-free ldmatrix)

// Pair table, bf16, in R8 consumption order (4-warp main kernel):
// uint4 index = p*512 + (j>>4)*128 + m*32 + (j&15)*2 + pp, holding elements
// i = pp*32+8m .. +8 of pairT[p][j][i] = sum_j' core[s1][i][j']*core[s2][j'][j].
__device__ __nv_bfloat16 g_pairT[NPAIR * D_DIM * D_DIM];    // 32 MB
// bf16 copies of core: row-major and transposed.
__device__ __nv_bfloat16 g_core_bf [NSYM * D_DIM * D_DIM];  // [s][i][j']
__device__ __nv_bfloat16 g_coreT_bf[NSYM * D_DIM * D_DIM];  // [s][j][j'] = core[s][j'][j]

// reinterpret a u32 as bf16x2 (via union; no pointer aliasing)
__device__ __forceinline__ __nv_bfloat162 u2bf2(unsigned int u) {
    union { unsigned int ui; __nv_bfloat162 b2; } cv;
    cv.ui = u;
    return cv.b2;
}
// pack two f32 into one bf16x2 u32: low 16 = lo (even index), high 16 = hi
__device__ __forceinline__ unsigned int bfpack(float lo, float hi) {
    unsigned int r;
    asm("cvt.rn.satfinite.bf16x2.f32 %0, %1, %2;" : "=r"(r) : "f"(hi), "f"(lo));
    return r;
}
static __device__ __forceinline__ uint32_t smem_u32(const void* p) {
    uint32_t a;
    asm("{ .reg .u64 t; cvta.to.shared.u64 t, %1; cvt.u32.u64 %0, t; }"
        : "=r"(a) : "l"(p));
    return a;
}

// ---------------------------------------------------------------------------
// Prep0: fp32 core -> bf16 row-major + bf16 transposed.
// ---------------------------------------------------------------------------
__global__ void ttrain_cvt_kernel(const float* __restrict__ core) {
    int idx = blockIdx.x * blockDim.x + threadIdx.x;
    if (idx < NSYM * D_DIM * D_DIM) {
        int s   = idx >> 12;
        int rem = idx & 4095;
        int i   = rem >> 6;      // row
        int jp  = rem & 63;      // col
        __nv_bfloat16 v = __float2bfloat16(core[idx]);
        g_core_bf[idx] = v;
        g_coreT_bf[(s << 12) + (jp << 6) + i] = v;
    }
}

// ---------------------------------------------------------------------------
// Prep1: pair-table build on tensor cores via mma.sync.m16n8k16 (bf16, fp32
// accum) — baseline PTX, no sm_103a-only features.  One CTA (4 warps) per
// pair p = s1*64 + s2.
//   D[j][i] = sum_k A[j][k] * B[i][k],  A = coreT_bf[s2] (M=64, row j),
//   B = core_bf[s1] (N=64, row i), K=64.  Warp w: m-rows [16w, 16w+16).
// Epilogue stores each lane's bf16x2 pairs straight into the R8 consumption
// layout (D-fragment columns are even/odd adjacent -> no staging needed).
// ---------------------------------------------------------------------------
__global__ __launch_bounds__(128) void ttrain_pair_mma_kernel() {
    __shared__ __align__(16) __nv_bfloat16 smA[D_DIM * PADROW];
    __shared__ __align__(16) __nv_bfloat16 smB[D_DIM * PADROW];

    const int tid = threadIdx.x;
    const int wid = tid >> 5;
    const int lid = tid & 31;
    const int p   = blockIdx.x;
    const int s1  = p >> 6;
    const int s2  = p & 63;

    // Stage A (transposed s2) and B (s1) into padded smem: 512 chunks of 16B.
    {
        const uint4* Ag = reinterpret_cast<const uint4*>(g_coreT_bf + (s2 << 12));
        const uint4* Bg = reinterpret_cast<const uint4*>(g_core_bf  + (s1 << 12));
        for (int c = tid; c < 512; c += 128) {
            int r  = c >> 3;
            int ch = c & 7;
            *reinterpret_cast<uint4*>(smA + r * PADROW + ch * 8) = Ag[c];
            *reinterpret_cast<uint4*>(smB + r * PADROW + ch * 8) = Bg[c];
        }
    }
    __syncthreads();

    const uint32_t smA_u = smem_u32(smA);
    const uint32_t smB_u = smem_u32(smB);
    const int m0 = wid << 4;                 // this warp's 16 m-rows

    float d[8][4];
#pragma unroll
    for (int n = 0; n < 8; ++n)
#pragma unroll
        for (int q = 0; q < 4; ++q) d[n][q] = 0.f;

#pragma unroll
    for (int k0 = 0; k0 < 64; k0 += 16) {
        // A fragment m16k16: ldmatrix.x4, lanes 0-15 rows m0..m0+15 @k0,
        // lanes 16-31 same rows @k0+8.
        uint32_t a0, a1, a2, a3;
        {
            int row  = m0 + (lid & 15);
            int koff = k0 + ((lid >> 4) << 3);
            uint32_t addr = smA_u + (row * PADROW + koff) * 2;
            asm volatile(
                "ldmatrix.sync.aligned.m8n8.x4.shared.b16 {%0,%1,%2,%3}, [%4];"
                : "=r"(a0), "=r"(a1), "=r"(a2), "=r"(a3) : "r"(addr));
        }
        // B fragments: one ldmatrix.x4 covers two n8k16 tiles (n0, n0+8).
#pragma unroll
        for (int nt = 0; nt < 4; ++nt) {
            const int n0 = nt << 4;
            uint32_t b0, b1, b2, b3;
            {
                int row  = n0 + (lid & 7) + ((lid >> 4) << 3);
                int koff = k0 + (((lid >> 3) & 1) << 3);
                uint32_t addr = smB_u + (row * PADROW + koff) * 2;
                asm volatile(
                    "ldmatrix.sync.aligned.m8n8.x4.shared.b16 {%0,%1,%2,%3}, [%4];"
                    : "=r"(b0), "=r"(b1), "=r"(b2), "=r"(b3) : "r"(addr));
            }
            asm volatile(
                "mma.sync.aligned.m16n8k16.row.col.f32.bf16.bf16.f32 "
                "{%0,%1,%2,%3}, {%4,%5,%6,%7}, {%8,%9}, {%0,%1,%2,%3};"
                : "+f"(d[2*nt][0]), "+f"(d[2*nt][1]),
                  "+f"(d[2*nt][2]), "+f"(d[2*nt][3])
                : "r"(a0), "r"(a1), "r"(a2), "r"(a3), "r"(b0), "r"(b1));
            asm volatile(
                "mma.sync.aligned.m16n8k16.row.col.f32.bf16.bf16.f32 "
                "{%0,%1,%2,%3}, {%4,%5,%6,%7}, {%8,%9}, {%0,%1,%2,%3};"
                : "+f"(d[2*nt+1][0]), "+f"(d[2*nt+1][1]),
                  "+f"(d[2*nt+1][2]), "+f"(d[2*nt+1][3])
                : "r"(a0), "r"(a1), "r"(a2), "r"(a3), "r"(b2), "r"(b3));
        }
    }

    // Epilogue: lane l holds rows j = m0 + (l>>2) and +8; cols i = 8*nt +
    // 2*(l&3) (+1).  bf16x2 (even i low) -> u32 slot of the R8 layout.
    {
        unsigned int* outw = reinterpret_cast<unsigned int*>(g_pairT);
        const int r  = lid >> 2;
        const int cc = (lid & 3) << 1;
        const int j_lo = m0 + r;
        const int j_hi = m0 + r + 8;
#pragma unroll
        for (int nt = 0; nt < 8; ++nt) {
            const int i = (nt << 3) + cc;
            // u32 index = 4*uint4_idx + (i&7)>>1, uint4_idx per layout comment.
            const int common = (p << 9) + (((i & 31) >> 3) << 5) + (i >> 5);
            const int idx_lo = ((common + ((j_lo >> 4) << 7) +
                                 ((j_lo & 15) << 1)) << 2) + ((i & 7) >> 1);
            const int idx_hi = ((common + ((j_hi >> 4) << 7) +
                                 ((j_hi & 15) << 1)) << 2) + ((i & 7) >> 1);
            outw[idx_lo] = bfpack(d[nt][0], d[nt][1]);
            outw[idx_hi] = bfpack(d[nt][2], d[nt][3]);
        }
    }
}

// ---------------------------------------------------------------------------
// Main chain (exact R8 kernel, 79.5us): one CTA (128 threads) per batch
// element, 512 fused steps.  warp w owns outputs j in [16w,16w+16); lane l:
// j = 16w + (l>>1), pp = l&1.  Thread does i in [32pp,32pp+32):
// 4 broadcast LDS.128 of bf16 c (issued FIRST) + 4 coalesced LDG.128
// prefetch (distance-3 ring) + 16 HFMA2, pair-combined via one shfl,
// bf16 store.  Renorm each step: exact power-of-two scale from the
// exponent of c[0] (cancels exactly in the final log).
// ---------------------------------------------------------------------------
__global__ __launch_bounds__(128, 1) void ttrain_main_kernel(
    const int*   __restrict__ X,
    const float* __restrict__ lb,
    const float* __restrict__ rb,
    float*       __restrict__ out)
{
    __shared__ __align__(16) unsigned short s_c[2][D_DIM];  // bf16 c, dbl-buf
    __shared__ float s_red[4];
    __shared__ int   sP[NSTEP];

    const int tid = threadIdx.x;
    const int b   = blockIdx.x;
    const int w   = tid >> 5;
    const int l   = tid & 31;
    const int pp  = l & 1;

    const int2* Xb2 = reinterpret_cast<const int2*>(X + b * S_LEN);
    for (int k = tid; k < NSTEP; k += 128) {
        int2 x2 = Xb2[k];
        sP[k] = (x2.x << 6) | x2.y;
    }
    if (tid < D_DIM)
        s_c[0][tid] = __bfloat16_as_ushort(__float2bfloat16(lb[tid]));
    __syncthreads();

    const uint4* wbase = reinterpret_cast<const uint4*>(g_pairT);
    const int    toff  = (w << 7) + l;

    uint4 ring[DEPTH][4];
#define LOADW(dst, tt) {                                                   \
        const uint4* pw_ = wbase + (sP[(tt) & (NSTEP - 1)] << 9) + toff;   \
        (dst)[0] = pw_[0];  (dst)[1] = pw_[32];                            \
        (dst)[2] = pw_[64]; (dst)[3] = pw_[96]; }

    LOADW(ring[0], 0)
    LOADW(ring[1], 1)
    LOADW(ring[2], 2)

    int e_total = 0;

    for (int t0 = 0; t0 < NSTEP; t0 += DEPTH) {
#pragma unroll
        for (int u = 0; u < DEPTH; ++u) {
            const int t   = t0 + u;
            const int buf = t & 1;

            unsigned short c0b = s_c[buf][0];
            const uint4* cv4 =
                reinterpret_cast<const uint4*>(&s_c[buf][pp << 5]);
            uint4 carr[4];
#pragma unroll
            for (int m = 0; m < 4; ++m) carr[m] = cv4[m];

            LOADW(ring[(u + DEPTH - 1) % DEPTH], t + DEPTH - 1)

            int ef = (c0b >> 7) & 0xff;
            int e  = (ef == 0) ? 0 : ef - 127;
            e = e < -96 ? -96 : (e > 96 ? 96 : e);
            e_total += e;
            const float scale = __int_as_float((127 - e) << 23);

            const uint4* wq = ring[u];

            __nv_bfloat162 a0 = __float2bfloat162_rn(0.f);
            __nv_bfloat162 a1 = __float2bfloat162_rn(0.f);
            __nv_bfloat162 a2 = __float2bfloat162_rn(0.f);
            __nv_bfloat162 a3 = __float2bfloat162_rn(0.f);
#pragma unroll
            for (int m = 0; m < 4; ++m) {
                a0 = __hfma2(u2bf2(carr[m].x), u2bf2(wq[m].x), a0);
                a1 = __hfma2(u2bf2(carr[m].y), u2bf2(wq[m].y), a1);
                a2 = __hfma2(u2bf2(carr[m].z), u2bf2(wq[m].z), a2);
                a3 = __hfma2(u2bf2(carr[m].w), u2bf2(wq[m].w), a3);
            }
            __nv_bfloat162 s01 = __hadd2(a0, a1);
            __nv_bfloat162 s23 = __hadd2(a2, a3);
            __nv_bfloat162 st  = __hadd2(s01, s23);
            float tot = __bfloat162float(__low2bfloat16(st)) +
                        __bfloat162float(__high2bfloat16(st));
            tot += __shfl_xor_sync(0xffffffffu, tot, 1);

            if (pp == 0)
                s_c[buf ^ 1][(w << 4) + (l >> 1)] =
                    __bfloat16_as_ushort(__float2bfloat16(tot * scale));
            __syncthreads();
        }
    }
#undef LOADW

    float v = 0.f;
    if (tid < D_DIM)
        v = __bfloat162float(__ushort_as_bfloat16(s_c[0][tid])) * rb[tid];
#pragma unroll
    for (int o = 16; o >= 1; o >>= 1)
        v += __shfl_xor_sync(0xffffffffu, v, o);
    if (l == 0) s_red[w] = v;
    __syncthreads();
    if (tid == 0) {
        double ov = (double)s_red[0] + (double)s_red[1] +
                    (double)s_red[2] + (double)s_red[3];
        out[b] = (float)(2.0 * ((double)e_total * 0.6931471805599453 +
                                log(fabs(ov))));
    }
}

extern "C" void kernel_launch(void* const* d_in, const int* in_sizes, int n_in,
                              void* d_out, int out_size) {
    // metadata order: X [128*1024] i32, core [64*64*64] f32,
    //                 left_boundary [64] f32, right_boundary [64] f32
    const int*   X    = (const int*)  d_in[0];
    const float* core = (const float*)d_in[1];
    const float* lb   = (const float*)d_in[2];
    const float* rb   = (const float*)d_in[3];
    float*       out  = (float*)d_out;

    ttrain_cvt_kernel<<<(NSYM * D_DIM * D_DIM + 255) / 256, 256>>>(core);
    ttrain_pair_mma_kernel<<<NPAIR, 128>>>();
    ttrain_main_kernel<<<128, 128>>>(X, lb, rb, out);
}